// round 3
// baseline (speedup 1.0000x reference)
#include <cuda_runtime.h>
#include <math.h>

// ---------------------------------------------------------------------------
// CellularAutomatonDecoder — fully fused, one CTA per batch row.
// B=2048, T=32, D=128, V=256, H=2D=256, 8 evolution steps.
// All matmuls via packed fp32 FFMA2 (fma.rn.f32x2), cells resident in SMEM.
// ---------------------------------------------------------------------------

#define Tn   32
#define Dn   128
#define Vn   256
#define Hn   256
#define NEVn 8

__device__ float g_cb[256];   // const_bias = rule_bias @ W1b + b1
__device__ float g_asig;      // sigmoid(alpha)

__device__ __forceinline__ unsigned long long dup2(float x) {
    unsigned long long r;
    asm("mov.b64 %0, {%1, %1};" : "=l"(r) : "f"(x));
    return r;
}
__device__ __forceinline__ unsigned long long pack2(float lo, float hi) {
    unsigned long long r;
    asm("mov.b64 %0, {%1, %2};" : "=l"(r) : "f"(lo), "f"(hi));
    return r;
}
__device__ __forceinline__ float2 unpack2(unsigned long long v) {
    float lo, hi;
    asm("mov.b64 {%0, %1}, %2;" : "=f"(lo), "=f"(hi) : "l"(v));
    return make_float2(lo, hi);
}
// d = a * b + d on two packed fp32 lanes (sm_103a FFMA2 path)
__device__ __forceinline__ void ffma2(unsigned long long& d,
                                      unsigned long long a,
                                      unsigned long long b) {
    asm("fma.rn.f32x2 %0, %1, %2, %0;" : "+l"(d) : "l"(a), "l"(b));
}

// exact (non-approximate) GELU, matches jax.nn.gelu(approximate=False)
__device__ __forceinline__ float gelu_exact(float x) {
    return 0.5f * x * (1.0f + erff(x * 0.70710678118654752440f));
}
// accurate tanh; expm1 form is small-x safe and immune to fast-math rewrites
__device__ __forceinline__ float tanh_acc(float x) {
    float ax  = fabsf(x);
    float em1 = expm1f(-2.0f * ax);      // in (-1, 0]
    float r   = -em1 / (em1 + 2.0f);
    return copysignf(r, x);
}

// ---------------------------------------------------------------------------
// Preamble (1 block): c_pooled -> rule_bias -> const_bias, sigmoid(alpha)
// ---------------------------------------------------------------------------
__global__ void ca_preamble(const float* __restrict__ c_states,
                            const float* __restrict__ W1,
                            const float* __restrict__ b1,
                            const float* __restrict__ Wc1,
                            const float* __restrict__ bc1,
                            const float* __restrict__ Wc2,
                            const float* __restrict__ bc2,
                            const float* __restrict__ alpha) {
    __shared__ float cp[128];
    __shared__ float h1[256];
    __shared__ float rb[128];
    const int tid = threadIdx.x;

    if (tid < 128)
        cp[tid] = 0.25f * (c_states[tid] + c_states[128 + tid] +
                           c_states[256 + tid] + c_states[384 + tid]);
    __syncthreads();

    {   // h1 = gelu(c_pooled @ Wc1 + bc1), 256 wide
        float s = bc1[tid];
        for (int k = 0; k < 128; ++k) s = fmaf(cp[k], Wc1[k * 256 + tid], s);
        h1[tid] = gelu_exact(s);
    }
    __syncthreads();

    if (tid < 128) {  // rule_bias = h1 @ Wc2 + bc2, 128 wide
        float r = bc2[tid];
        for (int j = 0; j < 256; ++j) r = fmaf(h1[j], Wc2[j * 128 + tid], r);
        rb[tid] = r;
    }
    __syncthreads();

    {   // const_bias = rule_bias @ W1b + b1  (W1b = rows 384..511 of W1)
        float s = b1[tid];
        for (int d = 0; d < 128; ++d)
            s = fmaf(rb[d], W1[(384 + d) * 256 + tid], s);
        g_cb[tid] = s;
    }
    if (tid == 0) g_asig = 1.0f / (1.0f + expf(-alpha[0]));
}

// ---------------------------------------------------------------------------
// Main fused kernel: one CTA (256 threads) per batch row.
// SMEM: cells sc[32][128] (16KB) + hidden sh[32][256] (32KB) = 48KB exactly.
// ---------------------------------------------------------------------------
__global__ void __launch_bounds__(256)
ca_main(const int*   __restrict__ tokens,
        const float* __restrict__ embed,
        const float* __restrict__ pos_embed,
        const float* __restrict__ W1,
        const float* __restrict__ W2,
        const float* __restrict__ b2,
        const float* __restrict__ ln_g,
        const float* __restrict__ ln_b,
        const float* __restrict__ head_w,
        float* __restrict__ out) {
    extern __shared__ float smem[];
    float* sc = smem;             // [32][128] cells
    float* sh = smem + 32 * 128;  // [32][256] hidden (gelu(pre))

    const int tid   = threadIdx.x;
    const int b     = blockIdx.x;
    const int lane5 = tid & 31;
    const int tt    = tid >> 5;
    const int t0    = tt * 4;       // 4 t-rows per thread in every phase
    const int j0    = lane5 * 8;    // GEMM1 / head: 8 output cols per thread
    const int d0    = lane5 * 4;    // GEMM2: 4 output dims per thread

    const float aev = g_asig;
    const float bev = 1.0f - aev;

    // ---- init cells: embed[tokens] + pos_embed
    const int* tok = tokens + b * Tn;
    for (int idx = tid; idx < Tn * Dn; idx += 256) {
        int t = idx >> 7;
        int d = idx & 127;
        sc[idx] = embed[tok[t] * Dn + d] + pos_embed[idx];
    }
    __syncthreads();

    // modular row offsets for {t-1 .. t+4}: rbase[s] = ((t0+s-1) mod 32)*128
    int rbase[6];
#pragma unroll
    for (int s2 = 0; s2 < 6; ++s2)
        rbase[s2] = (((t0 + s2 + 31) & 31) << 7);

    // =============== 8 evolution steps ===============
    for (int step = 0; step < NEVn; ++step) {
        // ---- GEMM1: pre = c@W1c + left@W1l + right@W1r + const_bias; sh = gelu(pre)
        unsigned long long acc[4][4];
        {
            unsigned long long c0 = pack2(g_cb[j0 + 0], g_cb[j0 + 1]);
            unsigned long long c1 = pack2(g_cb[j0 + 2], g_cb[j0 + 3]);
            unsigned long long c2 = pack2(g_cb[j0 + 4], g_cb[j0 + 5]);
            unsigned long long c3 = pack2(g_cb[j0 + 6], g_cb[j0 + 7]);
#pragma unroll
            for (int i = 0; i < 4; ++i) {
                acc[i][0] = c0; acc[i][1] = c1; acc[i][2] = c2; acc[i][3] = c3;
            }
        }
        const float* wcp = W1 + j0;              // center rows 0..127
        const float* wlp = W1 + 128 * 256 + j0;  // left   rows 128..255
        const float* wrp = W1 + 256 * 256 + j0;  // right  rows 256..383
#pragma unroll 4
        for (int k = 0; k < 128; ++k) {
            unsigned long long av[6];
#pragma unroll
            for (int s2 = 0; s2 < 6; ++s2) av[s2] = dup2(sc[rbase[s2] + k]);
            const ulonglong2* pc = reinterpret_cast<const ulonglong2*>(wcp + k * 256);
            const ulonglong2* pl = reinterpret_cast<const ulonglong2*>(wlp + k * 256);
            const ulonglong2* pr = reinterpret_cast<const ulonglong2*>(wrp + k * 256);
            ulonglong2 wc0 = pc[0], wc1 = pc[1];
            ulonglong2 wl0 = pl[0], wl1 = pl[1];
            ulonglong2 wr0 = pr[0], wr1 = pr[1];
#pragma unroll
            for (int i = 0; i < 4; ++i) {
                unsigned long long al = av[i], ac = av[i + 1], ar = av[i + 2];
                ffma2(acc[i][0], ac, wc0.x); ffma2(acc[i][1], ac, wc0.y);
                ffma2(acc[i][2], ac, wc1.x); ffma2(acc[i][3], ac, wc1.y);
                ffma2(acc[i][0], al, wl0.x); ffma2(acc[i][1], al, wl0.y);
                ffma2(acc[i][2], al, wl1.x); ffma2(acc[i][3], al, wl1.y);
                ffma2(acc[i][0], ar, wr0.x); ffma2(acc[i][1], ar, wr0.y);
                ffma2(acc[i][2], ar, wr1.x); ffma2(acc[i][3], ar, wr1.y);
            }
        }
#pragma unroll
        for (int i = 0; i < 4; ++i) {
            float* shr = sh + (t0 + i) * 256 + j0;
#pragma unroll
            for (int p = 0; p < 4; ++p) {
                float2 v = unpack2(acc[i][p]);
                shr[2 * p]     = gelu_exact(v.x);
                shr[2 * p + 1] = gelu_exact(v.y);
            }
        }
        __syncthreads();

        // ---- GEMM2: new = tanh(hidden @ W2 + b2); blend with EMA
        unsigned long long acc2[4][2];
        {
            unsigned long long p0 = pack2(b2[d0 + 0], b2[d0 + 1]);
            unsigned long long p1 = pack2(b2[d0 + 2], b2[d0 + 3]);
#pragma unroll
            for (int i = 0; i < 4; ++i) { acc2[i][0] = p0; acc2[i][1] = p1; }
        }
#pragma unroll 4
        for (int j = 0; j < 256; ++j) {
            const ulonglong2 w =
                *reinterpret_cast<const ulonglong2*>(W2 + j * 128 + d0);
#pragma unroll
            for (int i = 0; i < 4; ++i) {
                unsigned long long hv = dup2(sh[(t0 + i) * 256 + j]);
                ffma2(acc2[i][0], hv, w.x);
                ffma2(acc2[i][1], hv, w.y);
            }
        }
        float staged[4][4];
#pragma unroll
        for (int i = 0; i < 4; ++i) {
            const float* oldr = sc + (t0 + i) * 128 + d0;
            float2 v0 = unpack2(acc2[i][0]);
            float2 v1 = unpack2(acc2[i][1]);
            staged[i][0] = aev * oldr[0] + bev * tanh_acc(v0.x);
            staged[i][1] = aev * oldr[1] + bev * tanh_acc(v0.y);
            staged[i][2] = aev * oldr[2] + bev * tanh_acc(v1.x);
            staged[i][3] = aev * oldr[3] + bev * tanh_acc(v1.y);
        }
        __syncthreads();   // all old-cell reads done before any overwrite
#pragma unroll
        for (int i = 0; i < 4; ++i) {
            float* nr = sc + (t0 + i) * 128 + d0;
            nr[0] = staged[i][0]; nr[1] = staged[i][1];
            nr[2] = staged[i][2]; nr[3] = staged[i][3];
        }
        __syncthreads();
    }

    // ---- LayerNorm over D (warp w handles rows t0..t0+3; lane = 4 dims each)
#pragma unroll
    for (int rr = 0; rr < 4; ++rr) {
        int t = t0 + rr;
        float x0 = sc[t * 128 + lane5];
        float x1 = sc[t * 128 + 32 + lane5];
        float x2 = sc[t * 128 + 64 + lane5];
        float x3 = sc[t * 128 + 96 + lane5];
        float sm = x0 + x1 + x2 + x3;
        float sq = x0 * x0 + x1 * x1 + x2 * x2 + x3 * x3;
#pragma unroll
        for (int off = 16; off > 0; off >>= 1) {
            sm += __shfl_xor_sync(0xffffffffu, sm, off);
            sq += __shfl_xor_sync(0xffffffffu, sq, off);
        }
        float mu  = sm * (1.0f / 128.0f);
        float var = sq * (1.0f / 128.0f) - mu * mu;
        float rs  = rsqrtf(var + 1e-5f);
        sc[t * 128 + lane5]      = (x0 - mu) * rs * ln_g[lane5]      + ln_b[lane5];
        sc[t * 128 + 32 + lane5] = (x1 - mu) * rs * ln_g[lane5 + 32] + ln_b[lane5 + 32];
        sc[t * 128 + 64 + lane5] = (x2 - mu) * rs * ln_g[lane5 + 64] + ln_b[lane5 + 64];
        sc[t * 128 + 96 + lane5] = (x3 - mu) * rs * ln_g[lane5 + 96] + ln_b[lane5 + 96];
    }
    __syncthreads();

    // ---- Head: logits = cellsN @ head_w  (32 x 256)
    {
        unsigned long long ha[4][4];
#pragma unroll
        for (int i = 0; i < 4; ++i) {
            ha[i][0] = 0ULL; ha[i][1] = 0ULL; ha[i][2] = 0ULL; ha[i][3] = 0ULL;
        }
        const float* hb = head_w + j0;
#pragma unroll 4
        for (int k = 0; k < 128; ++k) {
            const ulonglong2* pw = reinterpret_cast<const ulonglong2*>(hb + k * 256);
            ulonglong2 w0 = pw[0], w1 = pw[1];
#pragma unroll
            for (int i = 0; i < 4; ++i) {
                unsigned long long xv = dup2(sc[(t0 + i) * 128 + k]);
                ffma2(ha[i][0], xv, w0.x); ffma2(ha[i][1], xv, w0.y);
                ffma2(ha[i][2], xv, w1.x); ffma2(ha[i][3], xv, w1.y);
            }
        }
        size_t ob = (size_t)b * (Tn * Vn);
#pragma unroll
        for (int i = 0; i < 4; ++i) {
            int t = t0 + i;
            float2 p0 = unpack2(ha[i][0]);
            float2 p1 = unpack2(ha[i][1]);
            float2 p2 = unpack2(ha[i][2]);
            float2 p3 = unpack2(ha[i][3]);
            float4* o = reinterpret_cast<float4*>(out + ob + (size_t)t * Vn + j0);
            o[0] = make_float4(p0.x, p0.y, p1.x, p1.y);
            o[1] = make_float4(p2.x, p2.y, p3.x, p3.y);
        }
    }
}

// ---------------------------------------------------------------------------
extern "C" void kernel_launch(void* const* d_in, const int* in_sizes, int n_in,
                              void* d_out, int out_size) {
    const int*   tokens    = (const int*)  d_in[0];
    const float* c_states  = (const float*)d_in[1];
    const float* embed     = (const float*)d_in[2];
    const float* pos_embed = (const float*)d_in[3];
    const float* W1        = (const float*)d_in[4];
    const float* b1        = (const float*)d_in[5];
    const float* W2        = (const float*)d_in[6];
    const float* b2        = (const float*)d_in[7];
    const float* Wc1       = (const float*)d_in[8];
    const float* bc1       = (const float*)d_in[9];
    const float* Wc2       = (const float*)d_in[10];
    const float* bc2       = (const float*)d_in[11];
    const float* alpha     = (const float*)d_in[12];
    const float* ln_g      = (const float*)d_in[13];
    const float* ln_b      = (const float*)d_in[14];
    const float* head_w    = (const float*)d_in[15];
    float* out = (float*)d_out;

    ca_preamble<<<1, 256>>>(c_states, W1, b1, Wc1, bc1, Wc2, bc2, alpha);
    // 48KB dynamic SMEM (exactly at the no-opt-in limit): sc 16KB + sh 32KB
    ca_main<<<2048, 256, 49152>>>(tokens, embed, pos_embed, W1, W2, b2,
                                  ln_g, ln_b, head_w, out);
}

// round 4
// speedup vs baseline: 2.3336x; 2.3336x over previous
#include <cuda_runtime.h>
#include <math.h>

// ---------------------------------------------------------------------------
// CellularAutomatonDecoder — fused, 2 batch rows per CTA, ghost-padded cells.
// B=2048, T=32, D=128, V=256, H=256, 8 evolution steps. fp32 FFMA2 everywhere.
// ---------------------------------------------------------------------------

typedef unsigned long long ull;

__device__ float g_cb[256];   // const_bias = rule_bias @ W1b + b1
__device__ float g_asig;      // sigmoid(alpha)

__device__ __forceinline__ ull dup2(float x) {
    ull r; asm("mov.b64 %0, {%1, %1};" : "=l"(r) : "f"(x)); return r;
}
__device__ __forceinline__ ull pack2(float lo, float hi) {
    ull r; asm("mov.b64 %0, {%1, %2};" : "=l"(r) : "f"(lo), "f"(hi)); return r;
}
__device__ __forceinline__ float2 unpack2(ull v) {
    float lo, hi; asm("mov.b64 {%0, %1}, %2;" : "=f"(lo), "=f"(hi) : "l"(v));
    return make_float2(lo, hi);
}
__device__ __forceinline__ void ffma2(ull& d, ull a, ull b) {
    asm("fma.rn.f32x2 %0, %1, %2, %0;" : "+l"(d) : "l"(a), "l"(b));
}

// exact (non-approximate) GELU, matches jax.nn.gelu(approximate=False)
__device__ __forceinline__ float gelu_exact(float x) {
    return 0.5f * x * (1.0f + erff(x * 0.70710678118654752440f));
}
// accurate tanh; expm1 form is small-x safe and immune to fast-math rewrites
__device__ __forceinline__ float tanh_acc(float x) {
    float ax  = fabsf(x);
    float em1 = expm1f(-2.0f * ax);
    float r   = -em1 / (em1 + 2.0f);
    return copysignf(r, x);
}

// ---------------------------------------------------------------------------
// Preamble (1 block): c_pooled -> rule_bias -> const_bias, sigmoid(alpha)
// ---------------------------------------------------------------------------
__global__ void ca_preamble(const float* __restrict__ c_states,
                            const float* __restrict__ W1,
                            const float* __restrict__ b1,
                            const float* __restrict__ Wc1,
                            const float* __restrict__ bc1,
                            const float* __restrict__ Wc2,
                            const float* __restrict__ bc2,
                            const float* __restrict__ alpha) {
    __shared__ float cp[128];
    __shared__ float h1[256];
    __shared__ float rb[128];
    const int tid = threadIdx.x;

    if (tid < 128)
        cp[tid] = 0.25f * (c_states[tid] + c_states[128 + tid] +
                           c_states[256 + tid] + c_states[384 + tid]);
    __syncthreads();
    {
        float s = bc1[tid];
        for (int k = 0; k < 128; ++k) s = fmaf(cp[k], Wc1[k * 256 + tid], s);
        h1[tid] = gelu_exact(s);
    }
    __syncthreads();
    if (tid < 128) {
        float r = bc2[tid];
        for (int j = 0; j < 256; ++j) r = fmaf(h1[j], Wc2[j * 128 + tid], r);
        rb[tid] = r;
    }
    __syncthreads();
    {
        float s = b1[tid];
        for (int d = 0; d < 128; ++d)
            s = fmaf(rb[d], W1[(384 + d) * 256 + tid], s);
        g_cb[tid] = s;
    }
    if (tid == 0) g_asig = 1.0f / (1.0f + expf(-alpha[0]));
}

// ---------------------------------------------------------------------------
// Main fused kernel. CTA = 256 threads, 2 batch rows. grid = 1024.
// SMEM: per row: cells padded [34][128] (ghost rows 0 and 33) + hidden [32][256]
//   sc_r at smem + r*4352 ; sh_r at smem + 8704 + r*8192 ; total 25088 f = 98KB
// Warp mapping (wid = r*4 + sub):
//   GEMM1/head: cg = sub&1 (128-col group), th = sub>>1 (16-row half),
//               thread = 16 t-rows x 4 cols (j0 = cg*128 + lane*4)
//   GEMM2/LN:   tb = sub (8-row block), thread = 8 t-rows x 4 dims (d0 = lane*4)
// ---------------------------------------------------------------------------
__global__ void __launch_bounds__(256, 2)
ca_main(const int*   __restrict__ tokens,
        const float* __restrict__ embed,
        const float* __restrict__ pos_embed,
        const float* __restrict__ W1,
        const float* __restrict__ W2,
        const float* __restrict__ b2,
        const float* __restrict__ ln_g,
        const float* __restrict__ ln_b,
        const float* __restrict__ head_w,
        float* __restrict__ out) {
    extern __shared__ float smem[];

    const int tid  = threadIdx.x;
    const int wid  = tid >> 5;
    const int lane = tid & 31;
    const int r    = wid >> 2;
    const int sub  = wid & 3;

    float* scr = smem + r * 4352;          // padded cells, rows 0..33
    float* shr = smem + 8704 + r * 8192;   // hidden [32][256]

    const int cg  = sub & 1;
    const int th  = sub >> 1;
    const int t0g = th * 16;
    const int j0  = cg * 128 + lane * 4;
    const int tb  = sub;
    const int t02 = tb * 8;
    const int d0  = lane * 4;

    const int b = blockIdx.x * 2 + r;

    // ---- init cells: embed[tokens] + pos_embed (padded rows 1..32)
    for (int idx = tid; idx < 8192; idx += 256) {
        int rr = idx >> 12;
        int e  = idx & 4095;
        int t  = e >> 7, d = e & 127;
        int bb = blockIdx.x * 2 + rr;
        smem[rr * 4352 + (t + 1) * 128 + d] =
            embed[tokens[bb * 32 + t] * 128 + d] + pos_embed[e];
    }
    __syncthreads();
    for (int idx = tid; idx < 512; idx += 256) {   // ghost rows
        int rr = idx >> 8, g = (idx >> 7) & 1, d = idx & 127;
        float* base = smem + rr * 4352;
        if (g) base[33 * 128 + d] = base[1 * 128 + d];     // row33 = t0
        else   base[d]            = base[32 * 128 + d];    // row0  = t31
    }
    __syncthreads();

    const float aev = g_asig;
    const float bev = 1.0f - aev;
    const ull cb0 = pack2(g_cb[j0],     g_cb[j0 + 1]);
    const ull cb1 = pack2(g_cb[j0 + 2], g_cb[j0 + 3]);
    const ull bb0 = pack2(b2[d0],     b2[d0 + 1]);
    const ull bb1 = pack2(b2[d0 + 2], b2[d0 + 3]);

    // =============== 8 evolution steps ===============
    for (int step = 0; step < 8; ++step) {
        // ---- GEMM1: pre = c@W1c + left@W1l + right@W1r + cb; sh = gelu(pre)
        ull acc[16][2];
#pragma unroll
        for (int t = 0; t < 16; ++t) { acc[t][0] = cb0; acc[t][1] = cb1; }
        {
            const float* wp = W1 + j0;
            const float* ap = scr + t0g * 128;
#pragma unroll 1
            for (int k2 = 0; k2 < 64; ++k2) {
                ulonglong2 wcA = *(const ulonglong2*)(wp);
                ulonglong2 wcB = *(const ulonglong2*)(wp + 256);
                ulonglong2 wlA = *(const ulonglong2*)(wp + 32768);
                ulonglong2 wlB = *(const ulonglong2*)(wp + 33024);
                ulonglong2 wrA = *(const ulonglong2*)(wp + 65536);
                ulonglong2 wrB = *(const ulonglong2*)(wp + 65792);
                float2 aP = *(const float2*)(ap);         // row t0-1 (padded t0)
                float2 aC = *(const float2*)(ap + 128);   // row t0
                ull dPx = dup2(aP.x), dPy = dup2(aP.y);
                ull dCx = dup2(aC.x), dCy = dup2(aC.y);
#pragma unroll
                for (int t = 0; t < 16; ++t) {
                    float2 aN = *(const float2*)(ap + (t + 2) * 128);
                    ull dNx = dup2(aN.x), dNy = dup2(aN.y);
                    ffma2(acc[t][0], dCx, wcA.x); ffma2(acc[t][1], dCx, wcA.y);
                    ffma2(acc[t][0], dPx, wlA.x); ffma2(acc[t][1], dPx, wlA.y);
                    ffma2(acc[t][0], dNx, wrA.x); ffma2(acc[t][1], dNx, wrA.y);
                    ffma2(acc[t][0], dCy, wcB.x); ffma2(acc[t][1], dCy, wcB.y);
                    ffma2(acc[t][0], dPy, wlB.x); ffma2(acc[t][1], dPy, wlB.y);
                    ffma2(acc[t][0], dNy, wrB.x); ffma2(acc[t][1], dNy, wrB.y);
                    dPx = dCx; dPy = dCy; dCx = dNx; dCy = dNy;
                }
                wp += 512;
                ap += 2;
            }
        }
#pragma unroll
        for (int t = 0; t < 16; ++t) {
            float2 v0 = unpack2(acc[t][0]);
            float2 v1 = unpack2(acc[t][1]);
            *(float4*)(shr + (t0g + t) * 256 + j0) =
                make_float4(gelu_exact(v0.x), gelu_exact(v0.y),
                            gelu_exact(v1.x), gelu_exact(v1.y));
        }
        __syncthreads();

        // ---- GEMM2: new = tanh(hidden @ W2 + b2); EMA blend into cells
        ull a2[8][2];
#pragma unroll
        for (int t = 0; t < 8; ++t) { a2[t][0] = bb0; a2[t][1] = bb1; }
        {
            const float* w2p = W2 + d0;
            const float* hp  = shr + t02 * 256;
#pragma unroll 1
            for (int k2 = 0; k2 < 128; ++k2) {
                ulonglong2 wA = *(const ulonglong2*)(w2p);
                ulonglong2 wB = *(const ulonglong2*)(w2p + 128);
#pragma unroll
                for (int t = 0; t < 8; ++t) {
                    float2 h = *(const float2*)(hp + t * 256);
                    ull hx = dup2(h.x), hy = dup2(h.y);
                    ffma2(a2[t][0], hx, wA.x); ffma2(a2[t][1], hx, wA.y);
                    ffma2(a2[t][0], hy, wB.x); ffma2(a2[t][1], hy, wB.y);
                }
                w2p += 256;
                hp  += 2;
            }
        }
#pragma unroll
        for (int t = 0; t < 8; ++t) {
            float* cp = scr + (t02 + t + 1) * 128 + d0;
            float4 o = *(float4*)cp;            // own cells only: no hazard
            float2 v0 = unpack2(a2[t][0]);
            float2 v1 = unpack2(a2[t][1]);
            float4 n;
            n.x = aev * o.x + bev * tanh_acc(v0.x);
            n.y = aev * o.y + bev * tanh_acc(v0.y);
            n.z = aev * o.z + bev * tanh_acc(v1.x);
            n.w = aev * o.w + bev * tanh_acc(v1.y);
            *(float4*)cp = n;
            int tg = t02 + t;
            if (tg == 0)  *(float4*)(scr + 33 * 128 + d0) = n;  // ghost top
            if (tg == 31) *(float4*)(scr + d0)            = n;  // ghost bottom
        }
        __syncthreads();
    }

    // ---- LayerNorm in place (padded rows 1..32); warp = 8 rows
    {
        float g0 = ln_g[lane],      g1 = ln_g[lane + 32];
        float g2 = ln_g[lane + 64], g3 = ln_g[lane + 96];
        float e0 = ln_b[lane],      e1 = ln_b[lane + 32];
        float e2 = ln_b[lane + 64], e3 = ln_b[lane + 96];
#pragma unroll
        for (int t = 0; t < 8; ++t) {
            float* p = scr + (t02 + t + 1) * 128;
            float x0 = p[lane], x1 = p[lane + 32];
            float x2 = p[lane + 64], x3 = p[lane + 96];
            float sm = x0 + x1 + x2 + x3;
            float sq = x0 * x0 + x1 * x1 + x2 * x2 + x3 * x3;
#pragma unroll
            for (int off = 16; off > 0; off >>= 1) {
                sm += __shfl_xor_sync(0xffffffffu, sm, off);
                sq += __shfl_xor_sync(0xffffffffu, sq, off);
            }
            float mu  = sm * (1.0f / 128.0f);
            float var = sq * (1.0f / 128.0f) - mu * mu;
            float rs  = rsqrtf(var + 1e-5f);
            p[lane]      = (x0 - mu) * rs * g0 + e0;
            p[lane + 32] = (x1 - mu) * rs * g1 + e1;
            p[lane + 64] = (x2 - mu) * rs * g2 + e2;
            p[lane + 96] = (x3 - mu) * rs * g3 + e3;
        }
    }
    __syncthreads();

    // ---- Head: logits = cellsN @ head_w  (32 x 256 per row)
    {
        ull ha[16][2];
#pragma unroll
        for (int t = 0; t < 16; ++t) { ha[t][0] = 0ULL; ha[t][1] = 0ULL; }
        const float* hwp = head_w + j0;
        const float* ap  = scr + (t0g + 1) * 128;
#pragma unroll 1
        for (int k2 = 0; k2 < 64; ++k2) {
            ulonglong2 wA = *(const ulonglong2*)(hwp);
            ulonglong2 wB = *(const ulonglong2*)(hwp + 256);
#pragma unroll
            for (int t = 0; t < 16; ++t) {
                float2 x = *(const float2*)(ap + t * 128);
                ull xx = dup2(x.x), xy = dup2(x.y);
                ffma2(ha[t][0], xx, wA.x); ffma2(ha[t][1], xx, wA.y);
                ffma2(ha[t][0], xy, wB.x); ffma2(ha[t][1], xy, wB.y);
            }
            hwp += 512;
            ap  += 2;
        }
        float* ob = out + ((size_t)b * 32 + t0g) * 256 + j0;
#pragma unroll
        for (int t = 0; t < 16; ++t) {
            float2 p0 = unpack2(ha[t][0]);
            float2 p1 = unpack2(ha[t][1]);
            *(float4*)(ob + (size_t)t * 256) =
                make_float4(p0.x, p0.y, p1.x, p1.y);
        }
    }
}

// ---------------------------------------------------------------------------
extern "C" void kernel_launch(void* const* d_in, const int* in_sizes, int n_in,
                              void* d_out, int out_size) {
    const int*   tokens    = (const int*)  d_in[0];
    const float* c_states  = (const float*)d_in[1];
    const float* embed     = (const float*)d_in[2];
    const float* pos_embed = (const float*)d_in[3];
    const float* W1        = (const float*)d_in[4];
    const float* b1        = (const float*)d_in[5];
    const float* W2        = (const float*)d_in[6];
    const float* b2        = (const float*)d_in[7];
    const float* Wc1       = (const float*)d_in[8];
    const float* bc1       = (const float*)d_in[9];
    const float* Wc2       = (const float*)d_in[10];
    const float* bc2       = (const float*)d_in[11];
    const float* alpha     = (const float*)d_in[12];
    const float* ln_g      = (const float*)d_in[13];
    const float* ln_b      = (const float*)d_in[14];
    const float* head_w    = (const float*)d_in[15];
    float* out = (float*)d_out;

    cudaFuncSetAttribute(ca_main, cudaFuncAttributeMaxDynamicSharedMemorySize,
                         100352);
    ca_preamble<<<1, 256>>>(c_states, W1, b1, Wc1, bc1, Wc2, bc2, alpha);
    ca_main<<<1024, 256, 100352>>>(tokens, embed, pos_embed, W1, W2, b2,
                                   ln_g, ln_b, head_w, out);
}